// round 1
// baseline (speedup 1.0000x reference)
#include <cuda_runtime.h>
#include <math.h>

#define Bb 256
#define Nn 512
#define Dd 64
#define TOK (Bb * Nn)        // 131072 tokens
#define TILES (TOK / 64)     // 2048 token tiles
#define PAD 68               // smem row pitch (floats): float4-aligned, conflict-light

// Scratch (allocation-free rule: __device__ globals). 8 x 33.5MB = 268MB.
__device__ float g_q[2][TOK * Dd];
__device__ float g_k[2][TOK * Dd];
__device__ float g_v[2][TOK * Dd];
__device__ float g_attn[2][TOK * Dd];

// ---------------------------------------------------------------------------
// Kernel 1: QKV projections for both branches.
// grid = (2048 token tiles, 6 weight matrices), 256 threads.
// C[64,64] = A[64,64] * W[64,64], 4x4 micro-tile per thread (16x16 threads).
// ---------------------------------------------------------------------------
__global__ __launch_bounds__(256) void proj_kernel(
    const float* __restrict__ x,
    const float* __restrict__ Wqt, const float* __restrict__ Wkt, const float* __restrict__ Wvt,
    const float* __restrict__ Wqs, const float* __restrict__ Wks, const float* __restrict__ Wvs)
{
    __shared__ float As[64][PAD];
    __shared__ float Bs[64][PAD];

    const int tile = blockIdx.x;
    const int w    = blockIdx.y;

    const float* W;
    float* out;
    switch (w) {
        case 0:  W = Wqt; out = g_q[0]; break;
        case 1:  W = Wkt; out = g_k[0]; break;
        case 2:  W = Wvt; out = g_v[0]; break;
        case 3:  W = Wqs; out = g_q[1]; break;
        case 4:  W = Wks; out = g_k[1]; break;
        default: W = Wvs; out = g_v[1]; break;
    }

    const int tid = threadIdx.x;
    const int ty = tid >> 4;
    const int tx = tid & 15;

    const float* xt = x + (size_t)tile * (64 * 64);

    // Load x tile and W into smem (float4, coalesced).
    for (int i = tid; i < 1024; i += 256) {
        int r = i >> 4;
        int c = (i & 15) << 2;
        *(float4*)&As[r][c] = *(const float4*)(xt + r * 64 + c);
        *(float4*)&Bs[r][c] = *(const float4*)(W + r * 64 + c);
    }
    __syncthreads();

    float acc[4][4] = {};
#pragma unroll 16
    for (int k = 0; k < 64; k++) {
        float a[4];
#pragma unroll
        for (int i = 0; i < 4; i++) a[i] = As[4 * ty + i][k];
        float4 b4 = *(float4*)&Bs[k][4 * tx];
        float bb[4] = {b4.x, b4.y, b4.z, b4.w};
#pragma unroll
        for (int i = 0; i < 4; i++)
#pragma unroll
            for (int j = 0; j < 4; j++)
                acc[i][j] += a[i] * bb[j];
    }

    float* ot = out + (size_t)tile * (64 * 64);
#pragma unroll
    for (int i = 0; i < 4; i++) {
        *(float4*)(ot + (4 * ty + i) * 64 + 4 * tx) =
            make_float4(acc[i][0], acc[i][1], acc[i][2], acc[i][3]);
    }
}

// ---------------------------------------------------------------------------
// Kernel 2: fused attention (flash-style online softmax) per (q-tile, batch, branch).
// grid = (8, 256, 2), 256 threads, dynamic smem = 3 * 64*PAD*4 = 52224 B.
// Buffers: Qs (scaled Q, natural), KT (K transposed d-major; reused as P), Vs.
// ---------------------------------------------------------------------------
__global__ __launch_bounds__(256) void attn_kernel()
{
    extern __shared__ float sm[];
    float (*Qs)[PAD] = (float(*)[PAD])sm;
    float (*KT)[PAD] = (float(*)[PAD])(sm + 64 * PAD);
    float (*Vs)[PAD] = (float(*)[PAD])(sm + 2 * 64 * PAD);
    float (*Ps)[PAD] = KT;  // P overwrites K after the S phase

    const int qt  = blockIdx.x;   // 0..7 query tile
    const int b   = blockIdx.y;   // batch
    const int br  = blockIdx.z;   // branch
    const int tid = threadIdx.x;
    const int ty  = tid >> 4;
    const int tx  = tid & 15;

    const float* Qg = g_q[br] + ((size_t)b * Nn + qt * 64) * Dd;
    const float* Kg = g_k[br] + (size_t)b * Nn * Dd;
    const float* Vg = g_v[br] + (size_t)b * Nn * Dd;

    const float scale = 0.125f;  // 1/sqrt(64), folded into Q

    for (int i = tid; i < 1024; i += 256) {
        int r = i >> 4;
        int c = (i & 15) << 2;
        float4 qv = *(const float4*)(Qg + r * 64 + c);
        qv.x *= scale; qv.y *= scale; qv.z *= scale; qv.w *= scale;
        *(float4*)&Qs[r][c] = qv;
    }

    float m[4], l[4], o[4][4];
#pragma unroll
    for (int i = 0; i < 4; i++) {
        m[i] = -1e30f;
        l[i] = 0.f;
#pragma unroll
        for (int j = 0; j < 4; j++) o[i][j] = 0.f;
    }

    for (int kt = 0; kt < 8; kt++) {
        __syncthreads();  // previous iteration's reads of KT/Vs done (also covers Qs fill)

        // Load K tile transposed (KT[d][key]) and V tile natural (Vs[key][d]).
        for (int i = tid; i < 1024; i += 256) {
            int r = i >> 4;           // key within tile
            int c = (i & 15) << 2;    // d
            float4 kv = *(const float4*)(Kg + (size_t)(kt * 64 + r) * 64 + c);
            KT[c + 0][r] = kv.x;
            KT[c + 1][r] = kv.y;
            KT[c + 2][r] = kv.z;
            KT[c + 3][r] = kv.w;
            *(float4*)&Vs[r][c] = *(const float4*)(Vg + (size_t)(kt * 64 + r) * 64 + c);
        }
        __syncthreads();

        // S = (Q*scale) . K^T  -> s[i][j], rows 4ty+i, keys 4tx+j
        float s[4][4] = {};
#pragma unroll 16
        for (int k = 0; k < 64; k++) {
            float a[4];
#pragma unroll
            for (int i = 0; i < 4; i++) a[i] = Qs[4 * ty + i][k];
            float4 b4 = *(float4*)&KT[k][4 * tx];
            float bb[4] = {b4.x, b4.y, b4.z, b4.w};
#pragma unroll
            for (int i = 0; i < 4; i++)
#pragma unroll
                for (int j = 0; j < 4; j++)
                    s[i][j] += a[i] * bb[j];
        }

        // Online softmax update (row stats replicated across the 16 tx lanes).
        float alpha[4];
#pragma unroll
        for (int i = 0; i < 4; i++) {
            float tm = fmaxf(fmaxf(s[i][0], s[i][1]), fmaxf(s[i][2], s[i][3]));
#pragma unroll
            for (int off = 8; off > 0; off >>= 1)
                tm = fmaxf(tm, __shfl_xor_sync(0xffffffffu, tm, off));
            float mnew = fmaxf(m[i], tm);
            alpha[i] = __expf(m[i] - mnew);
            m[i] = mnew;
        }
#pragma unroll
        for (int i = 0; i < 4; i++) {
            float ps = 0.f;
#pragma unroll
            for (int j = 0; j < 4; j++) {
                s[i][j] = __expf(s[i][j] - m[i]);
                ps += s[i][j];
            }
#pragma unroll
            for (int off = 8; off > 0; off >>= 1)
                ps += __shfl_xor_sync(0xffffffffu, ps, off);
            l[i] = l[i] * alpha[i] + ps;
#pragma unroll
            for (int j = 0; j < 4; j++) o[i][j] *= alpha[i];
        }

        __syncthreads();  // all S-phase reads of KT done before P overwrite
#pragma unroll
        for (int i = 0; i < 4; i++)
            *(float4*)&Ps[4 * ty + i][4 * tx] =
                make_float4(s[i][0], s[i][1], s[i][2], s[i][3]);
        __syncthreads();

        // O += P . V
#pragma unroll 16
        for (int k = 0; k < 64; k++) {
            float a[4];
#pragma unroll
            for (int i = 0; i < 4; i++) a[i] = Ps[4 * ty + i][k];
            float4 b4 = *(float4*)&Vs[k][4 * tx];
            float bb[4] = {b4.x, b4.y, b4.z, b4.w};
#pragma unroll
            for (int i = 0; i < 4; i++)
#pragma unroll
                for (int j = 0; j < 4; j++)
                    o[i][j] += a[i] * bb[j];
        }
    }

    float* Og = g_attn[br] + ((size_t)b * Nn + qt * 64) * Dd;
#pragma unroll
    for (int i = 0; i < 4; i++) {
        float inv = 1.f / l[i];
        *(float4*)(Og + (4 * ty + i) * 64 + 4 * tx) =
            make_float4(o[i][0] * inv, o[i][1] * inv, o[i][2] * inv, o[i][3] * inv);
    }
}

// ---------------------------------------------------------------------------
// Kernel 3: out = x * sigmoid(At*Wd_t + bd_t + As*Wd_s + bd_s)
// grid = 2048 token tiles, 256 threads.
// ---------------------------------------------------------------------------
__global__ __launch_bounds__(256) void gate_kernel(
    const float* __restrict__ x,
    const float* __restrict__ Wdt, const float* __restrict__ bdt,
    const float* __restrict__ Wds, const float* __restrict__ bds,
    float* __restrict__ out)
{
    __shared__ float As[64][PAD];
    __shared__ float Bs[64][PAD];

    const int tile = blockIdx.x;
    const int tid = threadIdx.x;
    const int ty = tid >> 4;
    const int tx = tid & 15;

    float acc[4][4] = {};

    for (int br = 0; br < 2; br++) {
        const float* A = g_attn[br] + (size_t)tile * 4096;
        const float* W = br ? Wds : Wdt;
        __syncthreads();  // guard smem reuse across br iterations
        for (int i = tid; i < 1024; i += 256) {
            int r = i >> 4;
            int c = (i & 15) << 2;
            *(float4*)&As[r][c] = *(const float4*)(A + r * 64 + c);
            *(float4*)&Bs[r][c] = *(const float4*)(W + r * 64 + c);
        }
        __syncthreads();
#pragma unroll 16
        for (int k = 0; k < 64; k++) {
            float a[4];
#pragma unroll
            for (int i = 0; i < 4; i++) a[i] = As[4 * ty + i][k];
            float4 b4 = *(float4*)&Bs[k][4 * tx];
            float bb[4] = {b4.x, b4.y, b4.z, b4.w};
#pragma unroll
            for (int i = 0; i < 4; i++)
#pragma unroll
                for (int j = 0; j < 4; j++)
                    acc[i][j] += a[i] * bb[j];
        }
    }

    float bias[4];
#pragma unroll
    for (int j = 0; j < 4; j++) bias[j] = bdt[4 * tx + j] + bds[4 * tx + j];

    const float* xt = x + (size_t)tile * 4096;
    float* ot = out + (size_t)tile * 4096;
#pragma unroll
    for (int i = 0; i < 4; i++) {
        float4 xv = *(const float4*)(xt + (4 * ty + i) * 64 + 4 * tx);
        float4 ov;
        ov.x = xv.x / (1.f + __expf(-(acc[i][0] + bias[0])));
        ov.y = xv.y / (1.f + __expf(-(acc[i][1] + bias[1])));
        ov.z = xv.z / (1.f + __expf(-(acc[i][2] + bias[2])));
        ov.w = xv.w / (1.f + __expf(-(acc[i][3] + bias[3])));
        *(float4*)(ot + (4 * ty + i) * 64 + 4 * tx) = ov;
    }
}

// ---------------------------------------------------------------------------
extern "C" void kernel_launch(void* const* d_in, const int* in_sizes, int n_in,
                              void* d_out, int out_size)
{
    const float* x   = (const float*)d_in[0];
    const float* Wqt = (const float*)d_in[1];
    const float* Wkt = (const float*)d_in[2];
    const float* Wvt = (const float*)d_in[3];
    const float* Wqs = (const float*)d_in[4];
    const float* Wks = (const float*)d_in[5];
    const float* Wvs = (const float*)d_in[6];
    const float* Wdt = (const float*)d_in[7];
    const float* bdt = (const float*)d_in[8];
    const float* Wds = (const float*)d_in[9];
    const float* bds = (const float*)d_in[10];
    float* out = (float*)d_out;

    dim3 g1(TILES, 6);
    proj_kernel<<<g1, 256>>>(x, Wqt, Wkt, Wvt, Wqs, Wks, Wvs);

    int smem2 = 3 * 64 * PAD * (int)sizeof(float);  // 52224 bytes
    cudaFuncSetAttribute(attn_kernel, cudaFuncAttributeMaxDynamicSharedMemorySize, smem2);
    dim3 g2(8, Bb, 2);
    attn_kernel<<<g2, 256, smem2>>>();

    gate_kernel<<<TILES, 256>>>(x, Wdt, bdt, Wds, bds, out);
}